// round 1
// baseline (speedup 1.0000x reference)
#include <cuda_runtime.h>
#include <cstddef>

// Problem constants
namespace {
constexpr int Bg    = 256;
constexpr int NUc   = 16;
constexpr int NTc   = 64;
constexpr int Hc    = 128;
constexpr int OUTF  = 32;
constexpr int NRFc  = 16;
constexpr int NUSER = Bg * NUc;   // 4096
constexpr int NAG   = Bg * NTc;   // 16384
}

// Scratch (device globals — no allocation allowed)
__device__ float g_hu  [NUSER * Hc];
__device__ float g_hu2 [NUSER * Hc];
__device__ float g_ha  [NAG   * Hc];
__device__ float g_ha2 [NAG   * Hc];
__device__ float g_tmpu[NUSER * Hc];
__device__ float g_tmpa[NAG   * Hc];
__device__ float g_mean[Bg    * Hc];
__device__ float g_hag [Bg    * Hc];

// ---------------------------------------------------------------------------
// Generic tiled GEMM:  C[M,128] = act( (A[M,K] (+ mean[row>>SHIFT])) @ W[K,128] + b )
// TM rows per block, 256 threads, each thread computes (TM/8) rows x 4 cols.
// A-tile loads in the main loop are warp-broadcast (all lanes share ty).
// ---------------------------------------------------------------------------
template<int K, int TM, bool RELU, int MEAN_SHIFT>
__global__ __launch_bounds__(256)
void gemm_h(const float* __restrict__ A,
            const float* __restrict__ W,      // [K][128] row-major
            const float* __restrict__ bias,   // [128]
            const float* __restrict__ mean,   // [256][128] or nullptr
            float* __restrict__ C)
{
    constexpr int RPT = TM / 8;
    extern __shared__ float smem[];
    float* sA = smem;            // TM*K
    float* sW = smem + TM * K;   // K*128

    const int tid  = threadIdx.x;
    const int tx   = tid & 31;          // column group: cols tx*4 .. tx*4+3
    const int ty   = tid >> 5;          // row group
    const int row0 = blockIdx.x * TM;

    // Load W tile (K*128 floats)
    {
        const float4* Wv = reinterpret_cast<const float4*>(W);
        float4* sWv = reinterpret_cast<float4*>(sW);
        #pragma unroll
        for (int i = tid; i < K * 32; i += 256) sWv[i] = Wv[i];
    }
    // Load A tile (optionally fused broadcast-add of group mean)
    {
        const float4* Av = reinterpret_cast<const float4*>(A + (size_t)row0 * K);
        float4* sAv = reinterpret_cast<float4*>(sA);
        constexpr int N4 = TM * K / 4;
        #pragma unroll
        for (int i = tid; i < N4; i += 256) {
            float4 v = Av[i];
            if constexpr (MEAN_SHIFT >= 0) {   // only used with K==128
                const int r = (i * 4) / K;
                const int k = (i * 4) % K;
                const int g = (row0 + r) >> MEAN_SHIFT;
                const float4 m = *reinterpret_cast<const float4*>(&mean[g * Hc + k]);
                v.x += m.x; v.y += m.y; v.z += m.z; v.w += m.w;
            }
            sAv[i] = v;
        }
    }
    __syncthreads();

    float acc[RPT][4];
    #pragma unroll
    for (int i = 0; i < RPT; ++i) { acc[i][0]=acc[i][1]=acc[i][2]=acc[i][3]=0.f; }

    #pragma unroll 4
    for (int k = 0; k < K; ++k) {
        const float4 w4 = *reinterpret_cast<const float4*>(&sW[k * Hc + tx * 4]);
        #pragma unroll
        for (int i = 0; i < RPT; ++i) {
            const float a = sA[(ty * RPT + i) * K + k];   // warp-broadcast
            acc[i][0] += a * w4.x;
            acc[i][1] += a * w4.y;
            acc[i][2] += a * w4.z;
            acc[i][3] += a * w4.w;
        }
    }

    const float4 b4 = *reinterpret_cast<const float4*>(&bias[tx * 4]);
    #pragma unroll
    for (int i = 0; i < RPT; ++i) {
        float4 c;
        c.x = acc[i][0] + b4.x;
        c.y = acc[i][1] + b4.y;
        c.z = acc[i][2] + b4.z;
        c.w = acc[i][3] + b4.w;
        if constexpr (RELU) {
            c.x = fmaxf(c.x, 0.f); c.y = fmaxf(c.y, 0.f);
            c.z = fmaxf(c.z, 0.f); c.w = fmaxf(c.w, 0.f);
        }
        *reinterpret_cast<float4*>(&C[(size_t)(row0 + ty * RPT + i) * Hc + tx * 4]) = c;
    }
}

// Group mean over GS consecutive rows: Mout[g][k] = mean_i A[g*GS+i][k]
template<int GS>
__global__ void group_mean(const float* __restrict__ A, float* __restrict__ Mout)
{
    const int idx = blockIdx.x * blockDim.x + threadIdx.x;  // 256*128 total
    const int g = idx >> 7;
    const int k = idx & 127;
    const float* p = A + (size_t)g * GS * Hc + k;
    float s = 0.f;
    #pragma unroll
    for (int i = 0; i < GS; ++i) s += p[i * Hc];
    Mout[idx] = s * (1.0f / GS);
}

// ha[row] = hag[row/64] + noise[row]   (float4 granularity)
__global__ void expand_add(const float* __restrict__ hag,
                           const float* __restrict__ noise,
                           float* __restrict__ ha)
{
    const int idx = blockIdx.x * blockDim.x + threadIdx.x;   // NAG*Hc/4
    const int k4  = idx & 31;
    const int row = idx >> 5;
    const int g   = row >> 6;
    float4 n = reinterpret_cast<const float4*>(noise)[idx];
    const float4 h = reinterpret_cast<const float4*>(hag)[g * 32 + k4];
    n.x += h.x; n.y += h.y; n.z += h.z; n.w += h.w;
    reinterpret_cast<float4*>(ha)[idx] = n;
}

// ---------------------------------------------------------------------------
// Final: f = ha @ W_norm + b_norm (no relu); out[row][r][{0,1}] = {re,im}/|f|
// 32 rows per block, 256 threads.
// ---------------------------------------------------------------------------
__global__ __launch_bounds__(256)
void final_norm(const float* __restrict__ ha,
                const float* __restrict__ W,     // [128][32]
                const float* __restrict__ bias,  // [32]
                float* __restrict__ out)
{
    constexpr int TM = 32;
    constexpr int PAD = 132;                 // padded stride: conflict-free A reads
    __shared__ float sA[TM * PAD];
    __shared__ float sW[Hc * OUTF];
    __shared__ float sF[TM * OUTF];

    const int tid  = threadIdx.x;
    const int row0 = blockIdx.x * TM;

    {
        const float4* Wv = reinterpret_cast<const float4*>(W);
        float4* sWv = reinterpret_cast<float4*>(sW);
        #pragma unroll
        for (int i = tid; i < Hc * OUTF / 4; i += 256) sWv[i] = Wv[i];
    }
    {
        const float4* Av = reinterpret_cast<const float4*>(ha + (size_t)row0 * Hc);
        #pragma unroll
        for (int i = tid; i < TM * 32; i += 256) {  // TM*128/4 float4s
            const int r  = i >> 5;
            const int k4 = i & 31;
            *reinterpret_cast<float4*>(&sA[r * PAD + k4 * 4]) = Av[i];
        }
    }
    __syncthreads();

    const int tx = tid & 7;     // col group: cols tx*4..tx*4+3
    const int ty = tid >> 3;    // row (0..31)
    float acc[4] = {0.f, 0.f, 0.f, 0.f};
    #pragma unroll 4
    for (int k = 0; k < Hc; ++k) {
        const float4 w4 = reinterpret_cast<const float4*>(sW)[k * 8 + tx];
        const float a = sA[ty * PAD + k];
        acc[0] += a * w4.x; acc[1] += a * w4.y;
        acc[2] += a * w4.z; acc[3] += a * w4.w;
    }
    const float4 b4 = *reinterpret_cast<const float4*>(&bias[tx * 4]);
    {
        float4 c;
        c.x = acc[0] + b4.x; c.y = acc[1] + b4.y;
        c.z = acc[2] + b4.z; c.w = acc[3] + b4.w;
        *reinterpret_cast<float4*>(&sF[ty * OUTF + tx * 4]) = c;
    }
    __syncthreads();

    // Normalize: 32 rows * 16 rf pairs
    #pragma unroll
    for (int i = tid; i < TM * NRFc; i += 256) {
        const int r   = i & 15;
        const int row = i >> 4;
        const float re = sF[row * OUTF + r];
        const float im = sF[row * OUTF + r + NRFc];
        const float inv = rsqrtf(re * re + im * im);
        float2 o; o.x = re * inv; o.y = im * inv;
        reinterpret_cast<float2*>(out)[(size_t)(row0 + row) * NRFc + r] = o;
    }
}

// ---------------------------------------------------------------------------
// Host
// ---------------------------------------------------------------------------
extern "C" void kernel_launch(void* const* d_in, const int* in_sizes, int n_in,
                              void* d_out, int out_size)
{
    (void)in_sizes; (void)n_in; (void)out_size;

    const float* user_feat = (const float*)d_in[0];
    const float* noise     = (const float*)d_in[1];
    // d_in[2..5] are the edge index arrays: structure is dense-per-group, unused.
    const float* W_ue     = (const float*)d_in[6],  *b_ue     = (const float*)d_in[7];
    const float* W_t      = (const float*)d_in[8],  *b_t      = (const float*)d_in[9];
    const float* W_aggr_a = (const float*)d_in[10], *b_aggr_a = (const float*)d_in[11];
    const float* W_self_a = (const float*)d_in[12], *b_self_a = (const float*)d_in[13];
    const float* W_comb_a = (const float*)d_in[14], *b_comb_a = (const float*)d_in[15];
    const float* W_aggr_u = (const float*)d_in[16], *b_aggr_u = (const float*)d_in[17];
    const float* W_self_u = (const float*)d_in[18], *b_self_u = (const float*)d_in[19];
    const float* W_comb_u = (const float*)d_in[20], *b_comb_u = (const float*)d_in[21];
    const float* W_norm   = (const float*)d_in[22], *b_norm   = (const float*)d_in[23];
    float* out = (float*)d_out;

    float *hu, *hu2, *ha, *ha2, *tmpu, *tmpa, *mean, *hag;
    cudaGetSymbolAddress((void**)&hu,   g_hu);
    cudaGetSymbolAddress((void**)&hu2,  g_hu2);
    cudaGetSymbolAddress((void**)&ha,   g_ha);
    cudaGetSymbolAddress((void**)&ha2,  g_ha2);
    cudaGetSymbolAddress((void**)&tmpu, g_tmpu);
    cudaGetSymbolAddress((void**)&tmpa, g_tmpa);
    cudaGetSymbolAddress((void**)&mean, g_mean);
    cudaGetSymbolAddress((void**)&hag,  g_hag);

    // Dynamic smem sizes per instantiation
    constexpr int SM_K32_TM32  = (32 * 32  + 32  * Hc) * 4;  // 20 KB
    constexpr int SM_K128_TM32 = (32 * 128 + 128 * Hc) * 4;  // 80 KB
    constexpr int SM_K128_TM64 = (64 * 128 + 128 * Hc) * 4;  // 96 KB

    cudaFuncSetAttribute((void*)gemm_h<128,32,true,-1>, cudaFuncAttributeMaxDynamicSharedMemorySize, SM_K128_TM32);
    cudaFuncSetAttribute((void*)gemm_h<128,32,true, 4>, cudaFuncAttributeMaxDynamicSharedMemorySize, SM_K128_TM32);
    cudaFuncSetAttribute((void*)gemm_h<128,64,true,-1>, cudaFuncAttributeMaxDynamicSharedMemorySize, SM_K128_TM64);
    cudaFuncSetAttribute((void*)gemm_h<128,64,true, 6>, cudaFuncAttributeMaxDynamicSharedMemorySize, SM_K128_TM64);

    // S1: hu = relu(user_feat @ W_ue + b_ue)        [4096,128]
    gemm_h<32,32,true,-1><<<NUSER/32, 256, SM_K32_TM32>>>(user_feat, W_ue, b_ue, nullptr, hu);
    // S2: per-group mean over 16 users -> [256,128]
    group_mean<16><<<Bg*Hc/256, 256>>>(hu, mean);
    // S3: hag = relu(mean @ W_t + b_t)              [256,128]
    gemm_h<128,32,true,-1><<<Bg/32, 256, SM_K128_TM32>>>(mean, W_t, b_t, nullptr, hag);
    // S4: ha = repeat(hag, 64) + noise              [16384,128]
    expand_add<<<NAG*Hc/4/256, 256>>>(hag, noise, ha);

    // ---- conv 1 (full) : (hu, ha) -> (hu2, ha2) ----
    // agent branch
    gemm_h<128,32,true,-1><<<NUSER/32, 256, SM_K128_TM32>>>(hu, W_aggr_a, b_aggr_a, nullptr, tmpu);
    group_mean<16><<<Bg*Hc/256, 256>>>(tmpu, mean);                      // m_a
    gemm_h<128,64,true,-1><<<NAG/64, 256, SM_K128_TM64>>>(ha, W_self_a, b_self_a, nullptr, tmpa);
    gemm_h<128,64,true, 6><<<NAG/64, 256, SM_K128_TM64>>>(tmpa, W_comb_a, b_comb_a, mean, ha2);
    // user branch
    gemm_h<128,64,true,-1><<<NAG/64, 256, SM_K128_TM64>>>(ha, W_aggr_u, b_aggr_u, nullptr, tmpa);
    group_mean<64><<<Bg*Hc/256, 256>>>(tmpa, mean);                      // m_u
    gemm_h<128,32,true,-1><<<NUSER/32, 256, SM_K128_TM32>>>(hu, W_self_u, b_self_u, nullptr, tmpu);
    gemm_h<128,32,true, 4><<<NUSER/32, 256, SM_K128_TM32>>>(tmpu, W_comb_u, b_comb_u, mean, hu2);

    // ---- conv 2 (agent branch only — user output is dead code) ----
    gemm_h<128,32,true,-1><<<NUSER/32, 256, SM_K128_TM32>>>(hu2, W_aggr_a, b_aggr_a, nullptr, tmpu);
    group_mean<16><<<Bg*Hc/256, 256>>>(tmpu, mean);
    gemm_h<128,64,true,-1><<<NAG/64, 256, SM_K128_TM64>>>(ha2, W_self_a, b_self_a, nullptr, tmpa);
    gemm_h<128,64,true, 6><<<NAG/64, 256, SM_K128_TM64>>>(tmpa, W_comb_a, b_comb_a, mean, ha);

    // ---- final: f = ha @ W_norm + b_norm, normalize re/im pairs ----
    final_norm<<<NAG/32, 256>>>(ha, W_norm, b_norm, out);
}

// round 3
// speedup vs baseline: 1.1638x; 1.1638x over previous
#include <cuda_runtime.h>
#include <cuda_bf16.h>
#include <cstdint>
#include <cstddef>

// ---------------------------------------------------------------------------
// Problem constants
// ---------------------------------------------------------------------------
namespace {
constexpr int Bg    = 256;
constexpr int Hc    = 128;
constexpr int OUTF  = 32;
constexpr int NRFc  = 16;
constexpr int NUSER = 4096;    // Bg*16
constexpr int NAG   = 16384;   // Bg*64
constexpr int APAD  = 136;     // padded bf16 row stride (272 B)
constexpr int TILEB = 128 * APAD * 2;   // 34816 B per bf16 tile
}

// ---------------------------------------------------------------------------
// Scratch (device globals — no allocation allowed)
// ---------------------------------------------------------------------------
__device__ float g_hu  [NUSER * Hc];
__device__ float g_hu2 [NUSER * Hc];
__device__ float g_ha  [NAG   * Hc];
__device__ float g_ha2 [NAG   * Hc];
__device__ float g_tmpu[NUSER * Hc];
__device__ float g_tmpa[NAG   * Hc];
__device__ float g_meanA[Bg * Hc];
__device__ float g_meanU[Bg * Hc];
__device__ float g_hag [Bg * Hc];
// Pre-transposed + hi/lo-split weights: 6 matrices of [n=128][k=128] bf16
__device__ __nv_bfloat16 g_wt_hi[6 * Hc * Hc];
__device__ __nv_bfloat16 g_wt_lo[6 * Hc * Hc];

// ---------------------------------------------------------------------------
// Helpers
// ---------------------------------------------------------------------------
__device__ __forceinline__ uint32_t smem_u32(const void* p) {
    uint32_t a;
    asm("{ .reg .u64 t; cvta.to.shared.u64 t, %1; cvt.u32.u64 %0, t; }"
        : "=r"(a) : "l"(p));
    return a;
}
__device__ __forceinline__ void ldsm4(uint32_t* r, uint32_t addr) {
    asm volatile("ldmatrix.sync.aligned.m8n8.x4.shared.b16 {%0,%1,%2,%3}, [%4];"
                 : "=r"(r[0]), "=r"(r[1]), "=r"(r[2]), "=r"(r[3]) : "r"(addr));
}
__device__ __forceinline__ void mma16816(float* d, const uint32_t* a, const uint32_t* b) {
    asm volatile(
        "mma.sync.aligned.m16n8k16.row.col.f32.bf16.bf16.f32 "
        "{%0,%1,%2,%3}, {%4,%5,%6,%7}, {%8,%9}, {%0,%1,%2,%3};"
        : "+f"(d[0]), "+f"(d[1]), "+f"(d[2]), "+f"(d[3])
        : "r"(a[0]), "r"(a[1]), "r"(a[2]), "r"(a[3]), "r"(b[0]), "r"(b[1]));
}
__device__ __forceinline__ uint32_t pack_bf2(__nv_bfloat16 a, __nv_bfloat16 b) {
    return (uint32_t)__bfloat16_as_ushort(a) | ((uint32_t)__bfloat16_as_ushort(b) << 16);
}

// ---------------------------------------------------------------------------
// Weight prep: Wt_hi/lo[m][n][k] (bf16) = split(W_m[k][n]); one block per matrix
// ---------------------------------------------------------------------------
__global__ __launch_bounds__(256, 1)
void prep_w(const float* W0, const float* W1, const float* W2,
            const float* W3, const float* W4, const float* W5,
            __nv_bfloat16* oh, __nv_bfloat16* ol)
{
    extern __shared__ float st[];   // [128][132]
    const float* Ws[6] = {W0, W1, W2, W3, W4, W5};
    const float* W = Ws[blockIdx.x];
    const int tid = threadIdx.x;

    for (int i = tid; i < Hc * 32; i += 256) {            // float4 units
        const int kr = i >> 5, c4 = i & 31;
        *reinterpret_cast<float4*>(&st[kr * 132 + c4 * 4]) =
            reinterpret_cast<const float4*>(W)[i];
    }
    __syncthreads();

    uint32_t* ph = reinterpret_cast<uint32_t*>(oh + (size_t)blockIdx.x * Hc * Hc);
    uint32_t* pl = reinterpret_cast<uint32_t*>(ol + (size_t)blockIdx.x * Hc * Hc);
    for (int i = tid; i < Hc * 64; i += 256) {            // bf16-pair units
        const int n = i >> 6, k2 = (i & 63) * 2;
        const float a = st[k2 * 132 + n];
        const float b = st[(k2 + 1) * 132 + n];
        const __nv_bfloat16 h0 = __float2bfloat16(a), h1 = __float2bfloat16(b);
        const float r0 = a - __bfloat162float(h0), r1 = b - __bfloat162float(h1);
        ph[n * 64 + (i & 63)] = pack_bf2(h0, h1);
        pl[n * 64 + (i & 63)] = pack_bf2(__float2bfloat16(r0), __float2bfloat16(r1));
    }
}

// ---------------------------------------------------------------------------
// HMMA GEMM: tile 128x128, 4 warps (warp tile 64x64), 3-pass bf16 hi/lo split.
//   MODE 0: C = relu(A@W + b)               -> full store
//   MODE 1: C = relu((A + mean_in[g])@W+b)  -> full store
//   MODE 2: output only per-group mean of relu(A@W+b)  (SHIFT=4 -> G=16, 6 -> G=64)
// ---------------------------------------------------------------------------
template<int MODE, int SHIFT>
__global__ __launch_bounds__(128, 1)
void gemm_mma(const float* __restrict__ A,
              const __nv_bfloat16* __restrict__ Wh,
              const __nv_bfloat16* __restrict__ Wl,
              const float* __restrict__ bias,
              const float* __restrict__ mean_in,
              float* __restrict__ outp)
{
    extern __shared__ char sm[];
    // tiles: Ah | Al | Bh | Bl, each 128 x APAD bf16
    char* pAh = sm;
    char* pAl = sm + TILEB;
    char* pBh = sm + 2 * TILEB;
    char* pBl = sm + 3 * TILEB;

    const int tid  = threadIdx.x;
    const int w    = tid >> 5, lane = tid & 31;
    const int row0 = blockIdx.x * 128;

    // ---- load B (pre-split [n][k] bf16) into padded smem
    {
        const uint4* wh = reinterpret_cast<const uint4*>(Wh);
        const uint4* wl = reinterpret_cast<const uint4*>(Wl);
        #pragma unroll
        for (int i = tid; i < 2048; i += 128) {           // 8-bf16 units
            const int n = i >> 4, k8 = i & 15;
            const uint32_t o = (uint32_t)(n * APAD * 2 + k8 * 16);
            *reinterpret_cast<uint4*>(pBh + o) = wh[i];
            *reinterpret_cast<uint4*>(pBl + o) = wl[i];
        }
    }
    // ---- load A (fp32, optional mean broadcast add), split hi/lo
    {
        #pragma unroll
        for (int i = tid; i < 2048; i += 128) {
            const int r = i >> 4, k = (i & 15) * 8;
            const float* ap = A + (size_t)(row0 + r) * Hc + k;
            float v[8];
            *reinterpret_cast<float4*>(&v[0]) = *reinterpret_cast<const float4*>(ap);
            *reinterpret_cast<float4*>(&v[4]) = *reinterpret_cast<const float4*>(ap + 4);
            if constexpr (MODE == 1) {
                const int g = (row0 + r) >> SHIFT;
                const float* mp = mean_in + g * Hc + k;
                float m[8];
                *reinterpret_cast<float4*>(&m[0]) = *reinterpret_cast<const float4*>(mp);
                *reinterpret_cast<float4*>(&m[4]) = *reinterpret_cast<const float4*>(mp + 4);
                #pragma unroll
                for (int j = 0; j < 8; ++j) v[j] += m[j];
            }
            uint32_t hb[4], lb[4];
            #pragma unroll
            for (int j = 0; j < 4; ++j) {
                const __nv_bfloat16 h0 = __float2bfloat16(v[2*j]);
                const __nv_bfloat16 h1 = __float2bfloat16(v[2*j+1]);
                const float r0 = v[2*j]   - __bfloat162float(h0);
                const float r1 = v[2*j+1] - __bfloat162float(h1);
                hb[j] = pack_bf2(h0, h1);
                lb[j] = pack_bf2(__float2bfloat16(r0), __float2bfloat16(r1));
            }
            const uint32_t o = (uint32_t)(r * APAD * 2 + (i & 15) * 16);
            *reinterpret_cast<uint4*>(pAh + o) = *reinterpret_cast<uint4*>(hb);
            *reinterpret_cast<uint4*>(pAl + o) = *reinterpret_cast<uint4*>(lb);
        }
    }
    __syncthreads();

    const uint32_t aAh = smem_u32(pAh), aAl = smem_u32(pAl);
    const uint32_t aBh = smem_u32(pBh), aBl = smem_u32(pBl);

    const int wm = w >> 1, wn = w & 1;
    const int m0 = wm * 64, n0 = wn * 64;

    // per-thread ldmatrix offsets (bytes)
    const int rr = lane & 7, quad = lane >> 3;
    const uint32_t a_off = (uint32_t)((m0 + rr + ((quad & 1) << 3)) * (APAD * 2)
                                      + ((quad & 2) << 3));          // +8 cols -> +16 B
    const uint32_t b_off = (uint32_t)((n0 + rr + ((quad >> 1) << 3)) * (APAD * 2)
                                      + ((quad & 1) << 4));          // +8 k -> +16 B

    float acc[4][8][4];
    #pragma unroll
    for (int mf = 0; mf < 4; ++mf)
        #pragma unroll
        for (int nf = 0; nf < 8; ++nf)
            acc[mf][nf][0] = acc[mf][nf][1] = acc[mf][nf][2] = acc[mf][nf][3] = 0.f;

    #pragma unroll
    for (int pass = 0; pass < 3; ++pass) {
        const uint32_t Ab = (pass == 2 ? aAl : aAh) + a_off;
        const uint32_t Bb = (pass == 1 ? aBl : aBh) + b_off;
        #pragma unroll
        for (int kc = 0; kc < 8; ++kc) {
            const uint32_t kb = (uint32_t)kc * 32;       // 16 bf16 = 32 B
            uint32_t af[4][4];
            #pragma unroll
            for (int mf = 0; mf < 4; ++mf)
                ldsm4(af[mf], Ab + (uint32_t)(mf * 16 * APAD * 2) + kb);
            uint32_t bf[8][2];
            #pragma unroll
            for (int p = 0; p < 4; ++p) {
                uint32_t t4[4];
                ldsm4(t4, Bb + (uint32_t)(p * 16 * APAD * 2) + kb);
                bf[2*p][0] = t4[0]; bf[2*p][1] = t4[1];
                bf[2*p+1][0] = t4[2]; bf[2*p+1][1] = t4[3];
            }
            #pragma unroll
            for (int mf = 0; mf < 4; ++mf)
                #pragma unroll
                for (int nf = 0; nf < 8; ++nf)
                    mma16816(acc[mf][nf], af[mf], bf[nf]);
        }
    }

    // ---- epilogue
    const int tq = lane & 3, gq = lane >> 2;     // C frag: rows gq/gq+8, cols 2tq/2tq+1
    float bv0[8], bv1[8];
    #pragma unroll
    for (int nf = 0; nf < 8; ++nf) {
        bv0[nf] = bias[n0 + nf * 8 + 2 * tq];
        bv1[nf] = bias[n0 + nf * 8 + 2 * tq + 1];
    }

    if constexpr (MODE <= 1) {
        #pragma unroll
        for (int mf = 0; mf < 4; ++mf) {
            const int r_lo = row0 + m0 + mf * 16 + gq;
            #pragma unroll
            for (int nf = 0; nf < 8; ++nf) {
                const int col = n0 + nf * 8 + 2 * tq;
                float2 lo, hi;
                lo.x = fmaxf(acc[mf][nf][0] + bv0[nf], 0.f);
                lo.y = fmaxf(acc[mf][nf][1] + bv1[nf], 0.f);
                hi.x = fmaxf(acc[mf][nf][2] + bv0[nf], 0.f);
                hi.y = fmaxf(acc[mf][nf][3] + bv1[nf], 0.f);
                *reinterpret_cast<float2*>(&outp[(size_t)r_lo * Hc + col]) = lo;
                *reinterpret_cast<float2*>(&outp[(size_t)(r_lo + 8) * Hc + col]) = hi;
            }
        }
    } else if constexpr (SHIFT == 4) {           // group = 16 rows = one m-frag
        #pragma unroll
        for (int mf = 0; mf < 4; ++mf) {
            const int grp = (row0 >> 4) + wm * 4 + mf;
            #pragma unroll
            for (int nf = 0; nf < 8; ++nf) {
                float s0 = fmaxf(acc[mf][nf][0] + bv0[nf], 0.f)
                         + fmaxf(acc[mf][nf][2] + bv0[nf], 0.f);
                float s1 = fmaxf(acc[mf][nf][1] + bv1[nf], 0.f)
                         + fmaxf(acc[mf][nf][3] + bv1[nf], 0.f);
                s0 += __shfl_xor_sync(0xffffffffu, s0, 4);
                s1 += __shfl_xor_sync(0xffffffffu, s1, 4);
                s0 += __shfl_xor_sync(0xffffffffu, s0, 8);
                s1 += __shfl_xor_sync(0xffffffffu, s1, 8);
                s0 += __shfl_xor_sync(0xffffffffu, s0, 16);
                s1 += __shfl_xor_sync(0xffffffffu, s1, 16);
                if (lane < 4) {
                    const int col = n0 + nf * 8 + 2 * lane;
                    float2 o2; o2.x = s0 * 0.0625f; o2.y = s1 * 0.0625f;
                    *reinterpret_cast<float2*>(&outp[grp * Hc + col]) = o2;
                }
            }
        }
    } else {                                     // group = 64 rows = one warp-tile M
        float s0[8], s1[8];
        #pragma unroll
        for (int nf = 0; nf < 8; ++nf) { s0[nf] = 0.f; s1[nf] = 0.f; }
        #pragma unroll
        for (int mf = 0; mf < 4; ++mf)
            #pragma unroll
            for (int nf = 0; nf < 8; ++nf) {
                s0[nf] += fmaxf(acc[mf][nf][0] + bv0[nf], 0.f)
                        + fmaxf(acc[mf][nf][2] + bv0[nf], 0.f);
                s1[nf] += fmaxf(acc[mf][nf][1] + bv1[nf], 0.f)
                        + fmaxf(acc[mf][nf][3] + bv1[nf], 0.f);
            }
        const int grp = (row0 >> 6) + wm;
        #pragma unroll
        for (int nf = 0; nf < 8; ++nf) {
            float a0 = s0[nf], a1 = s1[nf];
            a0 += __shfl_xor_sync(0xffffffffu, a0, 4);
            a1 += __shfl_xor_sync(0xffffffffu, a1, 4);
            a0 += __shfl_xor_sync(0xffffffffu, a0, 8);
            a1 += __shfl_xor_sync(0xffffffffu, a1, 8);
            a0 += __shfl_xor_sync(0xffffffffu, a0, 16);
            a1 += __shfl_xor_sync(0xffffffffu, a1, 16);
            if (lane < 4) {
                const int col = n0 + nf * 8 + 2 * lane;
                float2 o2; o2.x = a0 * (1.0f / 64.0f); o2.y = a1 * (1.0f / 64.0f);
                *reinterpret_cast<float2*>(&outp[grp * Hc + col]) = o2;
            }
        }
    }
}

// ---------------------------------------------------------------------------
// FFMA helpers for small/odd-shaped stages
// ---------------------------------------------------------------------------
template<int K, int TM>
__global__ __launch_bounds__(256)
void gemm_h(const float* __restrict__ A, const float* __restrict__ W,
            const float* __restrict__ bias, float* __restrict__ C)
{
    constexpr int RPT = TM / 8;
    extern __shared__ float smem[];
    float* sA = smem;
    float* sW = smem + TM * K;

    const int tid = threadIdx.x;
    const int tx = tid & 31, ty = tid >> 5;
    const int row0 = blockIdx.x * TM;

    {
        const float4* Wv = reinterpret_cast<const float4*>(W);
        float4* sWv = reinterpret_cast<float4*>(sW);
        #pragma unroll
        for (int i = tid; i < K * 32; i += 256) sWv[i] = Wv[i];
    }
    {
        const float4* Av = reinterpret_cast<const float4*>(A + (size_t)row0 * K);
        float4* sAv = reinterpret_cast<float4*>(sA);
        #pragma unroll
        for (int i = tid; i < TM * K / 4; i += 256) sAv[i] = Av[i];
    }
    __syncthreads();

    float acc[RPT][4];
    #pragma unroll
    for (int i = 0; i < RPT; ++i) acc[i][0]=acc[i][1]=acc[i][2]=acc[i][3]=0.f;

    #pragma unroll 4
    for (int k = 0; k < K; ++k) {
        const float4 w4 = *reinterpret_cast<const float4*>(&sW[k * Hc + tx * 4]);
        #pragma unroll
        for (int i = 0; i < RPT; ++i) {
            const float a = sA[(ty * RPT + i) * K + k];
            acc[i][0] += a * w4.x; acc[i][1] += a * w4.y;
            acc[i][2] += a * w4.z; acc[i][3] += a * w4.w;
        }
    }
    const float4 b4 = *reinterpret_cast<const float4*>(&bias[tx * 4]);
    #pragma unroll
    for (int i = 0; i < RPT; ++i) {
        float4 c;
        c.x = fmaxf(acc[i][0] + b4.x, 0.f);
        c.y = fmaxf(acc[i][1] + b4.y, 0.f);
        c.z = fmaxf(acc[i][2] + b4.z, 0.f);
        c.w = fmaxf(acc[i][3] + b4.w, 0.f);
        *reinterpret_cast<float4*>(&C[(size_t)(row0 + ty * RPT + i) * Hc + tx * 4]) = c;
    }
}

template<int GS>
__global__ void group_mean(const float* __restrict__ A, float* __restrict__ Mout)
{
    const int idx = blockIdx.x * blockDim.x + threadIdx.x;
    const int g = idx >> 7, k = idx & 127;
    const float* p = A + (size_t)g * GS * Hc + k;
    float s = 0.f;
    #pragma unroll
    for (int i = 0; i < GS; ++i) s += p[i * Hc];
    Mout[idx] = s * (1.0f / GS);
}

__global__ void expand_add(const float* __restrict__ hag,
                           const float* __restrict__ noise,
                           float* __restrict__ ha)
{
    const int idx = blockIdx.x * blockDim.x + threadIdx.x;
    const int k4 = idx & 31, row = idx >> 5, g = row >> 6;
    float4 n = reinterpret_cast<const float4*>(noise)[idx];
    const float4 h = reinterpret_cast<const float4*>(hag)[g * 32 + k4];
    n.x += h.x; n.y += h.y; n.z += h.z; n.w += h.w;
    reinterpret_cast<float4*>(ha)[idx] = n;
}

__global__ __launch_bounds__(256)
void final_norm(const float* __restrict__ ha, const float* __restrict__ W,
                const float* __restrict__ bias, float* __restrict__ out)
{
    constexpr int TM = 32, PAD = 132;
    __shared__ float sA[TM * PAD];
    __shared__ float sW[Hc * OUTF];
    __shared__ float sF[TM * OUTF];

    const int tid = threadIdx.x;
    const int row0 = blockIdx.x * TM;
    {
        const float4* Wv = reinterpret_cast<const float4*>(W);
        float4* sWv = reinterpret_cast<float4*>(sW);
        #pragma unroll
        for (int i = tid; i < Hc * OUTF / 4; i += 256) sWv[i] = Wv[i];
    }
    {
        const float4* Av = reinterpret_cast<const float4*>(ha + (size_t)row0 * Hc);
        #pragma unroll
        for (int i = tid; i < TM * 32; i += 256) {
            const int r = i >> 5, k4 = i & 31;
            *reinterpret_cast<float4*>(&sA[r * PAD + k4 * 4]) = Av[i];
        }
    }
    __syncthreads();

    const int tx = tid & 7, ty = tid >> 3;
    float acc[4] = {0.f, 0.f, 0.f, 0.f};
    #pragma unroll 4
    for (int k = 0; k < Hc; ++k) {
        const float4 w4 = reinterpret_cast<const float4*>(sW)[k * 8 + tx];
        const float a = sA[ty * PAD + k];
        acc[0] += a * w4.x; acc[1] += a * w4.y;
        acc[2] += a * w4.z; acc[3] += a * w4.w;
    }
    const float4 b4 = *reinterpret_cast<const float4*>(&bias[tx * 4]);
    {
        float4 c;
        c.x = acc[0] + b4.x; c.y = acc[1] + b4.y;
        c.z = acc[2] + b4.z; c.w = acc[3] + b4.w;
        *reinterpret_cast<float4*>(&sF[ty * OUTF + tx * 4]) = c;
    }
    __syncthreads();
    #pragma unroll
    for (int i = tid; i < TM * NRFc; i += 256) {
        const int r = i & 15, row = i >> 4;
        const float re = sF[row * OUTF + r];
        const float im = sF[row * OUTF + r + NRFc];
        const float inv = rsqrtf(re * re + im * im);
        float2 o; o.x = re * inv; o.y = im * inv;
        reinterpret_cast<float2*>(out)[(size_t)(row0 + row) * NRFc + r] = o;
    }
}

// ---------------------------------------------------------------------------
// Host
// ---------------------------------------------------------------------------
extern "C" void kernel_launch(void* const* d_in, const int* in_sizes, int n_in,
                              void* d_out, int out_size)
{
    (void)in_sizes; (void)n_in; (void)out_size;

    const float* user_feat = (const float*)d_in[0];
    const float* noise     = (const float*)d_in[1];
    const float* W_ue     = (const float*)d_in[6],  *b_ue     = (const float*)d_in[7];
    const float* W_t      = (const float*)d_in[8],  *b_t      = (const float*)d_in[9];
    const float* W_aggr_a = (const float*)d_in[10], *b_aggr_a = (const float*)d_in[11];
    const float* W_self_a = (const float*)d_in[12], *b_self_a = (const float*)d_in[13];
    const float* W_comb_a = (const float*)d_in[14], *b_comb_a = (const float*)d_in[15];
    const float* W_aggr_u = (const float*)d_in[16], *b_aggr_u = (const float*)d_in[17];
    const float* W_self_u = (const float*)d_in[18], *b_self_u = (const float*)d_in[19];
    const float* W_comb_u = (const float*)d_in[20], *b_comb_u = (const float*)d_in[21];
    const float* W_norm   = (const float*)d_in[22], *b_norm   = (const float*)d_in[23];
    float* out = (float*)d_out;

    float *hu, *hu2, *ha, *ha2, *tmpu, *tmpa, *meanA, *meanU, *hag;
    __nv_bfloat16 *wth, *wtl;
    cudaGetSymbolAddress((void**)&hu,    g_hu);
    cudaGetSymbolAddress((void**)&hu2,   g_hu2);
    cudaGetSymbolAddress((void**)&ha,    g_ha);
    cudaGetSymbolAddress((void**)&ha2,   g_ha2);
    cudaGetSymbolAddress((void**)&tmpu,  g_tmpu);
    cudaGetSymbolAddress((void**)&tmpa,  g_tmpa);
    cudaGetSymbolAddress((void**)&meanA, g_meanA);
    cudaGetSymbolAddress((void**)&meanU, g_meanU);
    cudaGetSymbolAddress((void**)&hag,   g_hag);
    cudaGetSymbolAddress((void**)&wth,   g_wt_hi);
    cudaGetSymbolAddress((void**)&wtl,   g_wt_lo);

    constexpr int SM_MMA  = 4 * TILEB;                    // 139264 B
    constexpr int SM_PREP = 128 * 132 * 4;                // 67.6 KB
    constexpr int SM_K32  = (32 * 32 + 32 * Hc) * 4;      // 20 KB
    constexpr int SM_K128 = (32 * 128 + 128 * Hc) * 4;    // 80 KB

    cudaFuncSetAttribute((void*)prep_w, cudaFuncAttributeMaxDynamicSharedMemorySize, SM_PREP);
    cudaFuncSetAttribute((void*)gemm_h<128,32>, cudaFuncAttributeMaxDynamicSharedMemorySize, SM_K128);
    cudaFuncSetAttribute((void*)gemm_mma<0,0>, cudaFuncAttributeMaxDynamicSharedMemorySize, SM_MMA);
    cudaFuncSetAttribute((void*)gemm_mma<1,6>, cudaFuncAttributeMaxDynamicSharedMemorySize, SM_MMA);
    cudaFuncSetAttribute((void*)gemm_mma<1,4>, cudaFuncAttributeMaxDynamicSharedMemorySize, SM_MMA);
    cudaFuncSetAttribute((void*)gemm_mma<2,4>, cudaFuncAttributeMaxDynamicSharedMemorySize, SM_MMA);
    cudaFuncSetAttribute((void*)gemm_mma<2,6>, cudaFuncAttributeMaxDynamicSharedMemorySize, SM_MMA);

    const __nv_bfloat16 *WH0 = wth + 0*16384, *WL0 = wtl + 0*16384;   // aggr_a
    const __nv_bfloat16 *WH1 = wth + 1*16384, *WL1 = wtl + 1*16384;   // self_a
    const __nv_bfloat16 *WH2 = wth + 2*16384, *WL2 = wtl + 2*16384;   // comb_a
    const __nv_bfloat16 *WH3 = wth + 3*16384, *WL3 = wtl + 3*16384;   // aggr_u
    const __nv_bfloat16 *WH4 = wth + 4*16384, *WL4 = wtl + 4*16384;   // self_u
    const __nv_bfloat16 *WH5 = wth + 5*16384, *WL5 = wtl + 5*16384;   // comb_u

    // 0) weight transpose + hi/lo split
    prep_w<<<6, 256, SM_PREP>>>(W_aggr_a, W_self_a, W_comb_a,
                                W_aggr_u, W_self_u, W_comb_u, wth, wtl);
    // 1) hu = relu(user_feat @ W_ue + b_ue)
    gemm_h<32,32><<<NUSER/32, 256, SM_K32>>>(user_feat, W_ue, b_ue, hu);
    // 2) group mean(16) of hu
    group_mean<16><<<Bg*Hc/256, 256>>>(hu, meanA);
    // 3) hag = relu(mean @ W_t + b_t)
    gemm_h<128,32><<<Bg/32, 256, SM_K128>>>(meanA, W_t, b_t, hag);
    // 4) ha = repeat(hag,64) + noise
    expand_add<<<NAG*Hc/4/256, 256>>>(hag, noise, ha);

    // ---- conv 1 ----
    gemm_mma<2,4><<<NUSER/128, 128, SM_MMA>>>(hu,  WH0, WL0, b_aggr_a, nullptr, meanA); // m_a
    gemm_mma<0,0><<<NAG/128,   128, SM_MMA>>>(ha,  WH1, WL1, b_self_a, nullptr, tmpa);
    gemm_mma<1,6><<<NAG/128,   128, SM_MMA>>>(tmpa,WH2, WL2, b_comb_a, meanA,   ha2);
    gemm_mma<2,6><<<NAG/128,   128, SM_MMA>>>(ha,  WH3, WL3, b_aggr_u, nullptr, meanU); // m_u
    gemm_mma<0,0><<<NUSER/128, 128, SM_MMA>>>(hu,  WH4, WL4, b_self_u, nullptr, tmpu);
    gemm_mma<1,4><<<NUSER/128, 128, SM_MMA>>>(tmpu,WH5, WL5, b_comb_u, meanU,   hu2);

    // ---- conv 2 (agent branch only; user branch is dead code) ----
    gemm_mma<2,4><<<NUSER/128, 128, SM_MMA>>>(hu2, WH0, WL0, b_aggr_a, nullptr, meanA);
    gemm_mma<0,0><<<NAG/128,   128, SM_MMA>>>(ha2, WH1, WL1, b_self_a, nullptr, tmpa);
    gemm_mma<1,6><<<NAG/128,   128, SM_MMA>>>(tmpa,WH2, WL2, b_comb_a, meanA,   ha);

    // ---- final projection + normalize ----
    final_norm<<<NAG/32, 256>>>(ha, W_norm, b_norm, out);
}

// round 4
// speedup vs baseline: 1.8242x; 1.5675x over previous
#include <cuda_runtime.h>
#include <cuda_bf16.h>
#include <cstdint>
#include <cstddef>

// ---------------------------------------------------------------------------
// Problem constants
// ---------------------------------------------------------------------------
namespace {
constexpr int Bg    = 256;
constexpr int Hc    = 128;
constexpr int NRFc  = 16;
constexpr int NUSER = 4096;    // Bg*16
constexpr int NAG   = 16384;   // Bg*64
constexpr int APAD  = 136;     // bf16 elems per smem row
constexpr int ASTR  = APAD * 2; // 272 bytes
}

// ---------------------------------------------------------------------------
// Scratch (device globals — no allocation allowed)
// ---------------------------------------------------------------------------
__device__ float g_hu  [NUSER * Hc];
__device__ float g_hu2 [NUSER * Hc];
__device__ float g_ha2 [NAG   * Hc];
__device__ float g_meanA[Bg * Hc];
__device__ float g_meanU[Bg * Hc];
__device__ float g_hag [Bg * Hc];
// Pre-transposed + hi/lo-split weights: slots 0..5 = H x H, slot 6 = W_norm (64x128 used)
__device__ __nv_bfloat16 g_wt_hi[7 * Hc * Hc];
__device__ __nv_bfloat16 g_wt_lo[7 * Hc * Hc];

// ---------------------------------------------------------------------------
// Helpers
// ---------------------------------------------------------------------------
__device__ __forceinline__ uint32_t smem_u32(const void* p) {
    uint32_t a;
    asm("{ .reg .u64 t; cvta.to.shared.u64 t, %1; cvt.u32.u64 %0, t; }"
        : "=r"(a) : "l"(p));
    return a;
}
__device__ __forceinline__ void ldsm4(uint32_t* r, uint32_t addr) {
    asm volatile("ldmatrix.sync.aligned.m8n8.x4.shared.b16 {%0,%1,%2,%3}, [%4];"
                 : "=r"(r[0]), "=r"(r[1]), "=r"(r[2]), "=r"(r[3]) : "r"(addr));
}
__device__ __forceinline__ void mma16816(float* d, const uint32_t* a, const uint32_t* b) {
    asm volatile(
        "mma.sync.aligned.m16n8k16.row.col.f32.bf16.bf16.f32 "
        "{%0,%1,%2,%3}, {%4,%5,%6,%7}, {%8,%9}, {%0,%1,%2,%3};"
        : "+f"(d[0]), "+f"(d[1]), "+f"(d[2]), "+f"(d[3])
        : "r"(a[0]), "r"(a[1]), "r"(a[2]), "r"(a[3]), "r"(b[0]), "r"(b[1]));
}
__device__ __forceinline__ uint32_t pack_bf2(__nv_bfloat16 a, __nv_bfloat16 b) {
    return (uint32_t)__bfloat16_as_ushort(a) | ((uint32_t)__bfloat16_as_ushort(b) << 16);
}
__device__ __forceinline__ void split2(float a, float b, uint32_t& hi, uint32_t& lo) {
    const __nv_bfloat16 h0 = __float2bfloat16(a), h1 = __float2bfloat16(b);
    hi = pack_bf2(h0, h1);
    lo = pack_bf2(__float2bfloat16(a - __bfloat162float(h0)),
                  __float2bfloat16(b - __bfloat162float(h1)));
}

// A tile load: fp32 (+optional hag broadcast, group = row>>6), hi/lo split to smem
template<int TM, bool ADD>
__device__ __forceinline__ void load_split_A(const float* __restrict__ A,
                                             const float* __restrict__ addv,
                                             int row0, char* pAh, char* pAl, int tid)
{
    #pragma unroll
    for (int i = tid; i < TM * 16; i += 256) {
        const int r = i >> 4, k = (i & 15) * 8;
        const float* ap = A + (size_t)(row0 + r) * Hc + k;
        float v[8];
        *reinterpret_cast<float4*>(&v[0]) = *reinterpret_cast<const float4*>(ap);
        *reinterpret_cast<float4*>(&v[4]) = *reinterpret_cast<const float4*>(ap + 4);
        if (ADD) {
            const float* mp = addv + ((row0 + r) >> 6) * Hc + k;
            float m[8];
            *reinterpret_cast<float4*>(&m[0]) = *reinterpret_cast<const float4*>(mp);
            *reinterpret_cast<float4*>(&m[4]) = *reinterpret_cast<const float4*>(mp + 4);
            #pragma unroll
            for (int j = 0; j < 8; ++j) v[j] += m[j];
        }
        uint32_t hb[4], lb[4];
        #pragma unroll
        for (int j = 0; j < 4; ++j) split2(v[2*j], v[2*j+1], hb[j], lb[j]);
        const uint32_t o = (uint32_t)(r * ASTR + (i & 15) * 16);
        *reinterpret_cast<uint4*>(pAh + o) = *reinterpret_cast<uint4*>(hb);
        *reinterpret_cast<uint4*>(pAl + o) = *reinterpret_cast<uint4*>(lb);
    }
}

template<int NROWS>
__device__ __forceinline__ void load_B(const __nv_bfloat16* __restrict__ Wh,
                                       const __nv_bfloat16* __restrict__ Wl,
                                       char* pBh, char* pBl, int tid)
{
    const uint4* wh = reinterpret_cast<const uint4*>(Wh);
    const uint4* wl = reinterpret_cast<const uint4*>(Wl);
    #pragma unroll
    for (int i = tid; i < NROWS * 16; i += 256) {
        const uint32_t o = (uint32_t)((i >> 4) * ASTR + (i & 15) * 16);
        *reinterpret_cast<uint4*>(pBh + o) = wh[i];
        *reinterpret_cast<uint4*>(pBl + o) = wl[i];
    }
}

// 3-pass hi/lo MMA over K=128: acc += (Ah+Al)@(Bh+Bl) minus Al*Bl
template<int MF, int NF>
__device__ __forceinline__ void mma_3p(uint32_t aAh, uint32_t aAl,
                                       uint32_t aBh, uint32_t aBl,
                                       uint32_t a_off, uint32_t b_off,
                                       float (*acc)[NF][4])
{
    #pragma unroll
    for (int pass = 0; pass < 3; ++pass) {
        const uint32_t Ab = (pass == 2 ? aAl : aAh) + a_off;
        const uint32_t Bb = (pass == 1 ? aBl : aBh) + b_off;
        #pragma unroll
        for (int kc = 0; kc < 8; ++kc) {
            const uint32_t kb = (uint32_t)kc * 32;
            uint32_t af[MF][4];
            #pragma unroll
            for (int mf = 0; mf < MF; ++mf)
                ldsm4(af[mf], Ab + (uint32_t)(mf * 16 * ASTR) + kb);
            uint32_t bfr[NF][2];
            #pragma unroll
            for (int p = 0; p < NF / 2; ++p) {
                uint32_t t[4];
                ldsm4(t, Bb + (uint32_t)(p * 16 * ASTR) + kb);
                bfr[2*p][0] = t[0]; bfr[2*p][1] = t[1];
                bfr[2*p+1][0] = t[2]; bfr[2*p+1][1] = t[3];
            }
            #pragma unroll
            for (int mf = 0; mf < MF; ++mf)
                #pragma unroll
                for (int nf = 0; nf < NF; ++nf)
                    mma16816(acc[mf][nf], af[mf], bfr[nf]);
        }
    }
}

// ---------------------------------------------------------------------------
// Weight prep: slots 0..5: Wt[n][k] hi/lo from W[k][n] (128x128)
// slot 6: W_norm [128][32] -> permuted-transposed [64][128] (rows 32..63 zero),
//         row' = 2*(n&15) + (n>>4)  (re/im interleave for the fused final epilogue)
// ---------------------------------------------------------------------------
__global__ __launch_bounds__(256, 1)
void prep_w(const float* W0, const float* W1, const float* W2,
            const float* W3, const float* W4, const float* W5,
            const float* Wn,
            __nv_bfloat16* oh, __nv_bfloat16* ol)
{
    extern __shared__ float st[];
    const int tid = threadIdx.x;
    const int m = blockIdx.x;
    uint32_t* ph = reinterpret_cast<uint32_t*>(oh + (size_t)m * Hc * Hc);
    uint32_t* pl = reinterpret_cast<uint32_t*>(ol + (size_t)m * Hc * Hc);

    if (m < 6) {
        const float* Ws[6] = {W0, W1, W2, W3, W4, W5};
        const float* W = Ws[m];
        for (int i = tid; i < Hc * 32; i += 256) {
            const int kr = i >> 5, c4 = i & 31;
            *reinterpret_cast<float4*>(&st[kr * 132 + c4 * 4]) =
                reinterpret_cast<const float4*>(W)[i];
        }
        __syncthreads();
        for (int i = tid; i < Hc * 64; i += 256) {
            const int n = i >> 6, k2 = (i & 63) * 2;
            const float a = st[k2 * 132 + n];
            const float b = st[(k2 + 1) * 132 + n];
            uint32_t hi, lo;
            split2(a, b, hi, lo);
            ph[n * 64 + (i & 63)] = hi;
            pl[n * 64 + (i & 63)] = lo;
        }
    } else {
        // W_norm [128][32]
        for (int i = tid; i < Hc * 8; i += 256) {
            const int kr = i >> 3, c4 = i & 7;
            *reinterpret_cast<float4*>(&st[kr * 36 + c4 * 4]) =
                reinterpret_cast<const float4*>(Wn)[i];
        }
        __syncthreads();
        for (int i = tid; i < 64 * 64; i += 256) {
            const int rowp = i >> 6, k = (i & 63) * 2;
            uint32_t hi = 0, lo = 0;
            if (rowp < 32) {
                const int n = (rowp & 1) * 16 + (rowp >> 1);
                split2(st[k * 36 + n], st[(k + 1) * 36 + n], hi, lo);
            }
            ph[rowp * 64 + (i & 63)] = hi;
            pl[rowp * 64 + (i & 63)] = lo;
        }
    }
}

// ---------------------------------------------------------------------------
// stage1: hu = relu(uf@W_ue+b_ue) (store), group-16 mean in smem,
//         hag = relu(mean@W_t+b_t) (store, 8 group-rows per block)
// ---------------------------------------------------------------------------
__global__ __launch_bounds__(256, 1)
void stage1(const float* __restrict__ uf,
            const float* __restrict__ W_ue, const float* __restrict__ b_ue,
            const float* __restrict__ W_t,  const float* __restrict__ b_t,
            float* __restrict__ hu, float* __restrict__ hag)
{
    extern __shared__ char sm[];
    float* sA    = reinterpret_cast<float*>(sm);            // [128][36]
    float* sW    = reinterpret_cast<float*>(sm + 18432);    // W_ue [32][128]
    float* smean = reinterpret_cast<float*>(sm + 65536);    // [8][132]
    float* sWt   = reinterpret_cast<float*>(sm);            // phase2: W_t [128][128]

    const int tid = threadIdx.x;
    const int row0 = blockIdx.x * 128;

    for (int i = tid; i < 1024; i += 256) {
        const int r = i >> 3, k4 = i & 7;
        *reinterpret_cast<float4*>(&sA[r * 36 + k4 * 4]) =
            reinterpret_cast<const float4*>(uf)[(size_t)row0 * 8 + i];
    }
    for (int i = tid; i < 1024; i += 256)
        reinterpret_cast<float4*>(sW)[i] = reinterpret_cast<const float4*>(W_ue)[i];
    __syncthreads();

    const int tx = tid & 31, ty = tid >> 5;
    const float4 b4 = reinterpret_cast<const float4*>(b_ue)[tx];
    float4 msum = {0.f, 0.f, 0.f, 0.f};
    #pragma unroll 4
    for (int i = 0; i < 16; ++i) {
        const int r = ty * 16 + i;
        float4 acc = b4;
        #pragma unroll
        for (int k = 0; k < 32; ++k) {
            const float a = sA[r * 36 + k];
            const float4 w = reinterpret_cast<const float4*>(sW)[k * 32 + tx];
            acc.x += a * w.x; acc.y += a * w.y; acc.z += a * w.z; acc.w += a * w.w;
        }
        acc.x = fmaxf(acc.x, 0.f); acc.y = fmaxf(acc.y, 0.f);
        acc.z = fmaxf(acc.z, 0.f); acc.w = fmaxf(acc.w, 0.f);
        reinterpret_cast<float4*>(hu)[(size_t)(row0 + r) * 32 + tx] = acc;
        msum.x += acc.x; msum.y += acc.y; msum.z += acc.z; msum.w += acc.w;
    }
    {
        float4 mv = {msum.x * 0.0625f, msum.y * 0.0625f,
                     msum.z * 0.0625f, msum.w * 0.0625f};
        *reinterpret_cast<float4*>(&smean[ty * 132 + tx * 4]) = mv;
    }
    __syncthreads();
    // phase 2
    for (int i = tid; i < 4096; i += 256)
        reinterpret_cast<float4*>(sWt)[i] = reinterpret_cast<const float4*>(W_t)[i];
    __syncthreads();
    {
        const int col4 = tid & 31, gr = tid >> 5;
        float4 acc = reinterpret_cast<const float4*>(b_t)[col4];
        #pragma unroll 4
        for (int k = 0; k < 128; ++k) {
            const float a = smean[gr * 132 + k];
            const float4 w = reinterpret_cast<const float4*>(sWt)[k * 32 + col4];
            acc.x += a * w.x; acc.y += a * w.y; acc.z += a * w.z; acc.w += a * w.w;
        }
        acc.x = fmaxf(acc.x, 0.f); acc.y = fmaxf(acc.y, 0.f);
        acc.z = fmaxf(acc.z, 0.f); acc.w = fmaxf(acc.w, 0.f);
        reinterpret_cast<float4*>(hag)[(size_t)(blockIdx.x * 8 + gr) * 32 + col4] = acc;
    }
}

// ---------------------------------------------------------------------------
// Single GEMM producing only the group mean of relu(A@W+b).
//  OUTMODE 1: group=16 rows (per-mf). OUTMODE 2: group=64 rows (per warp-tile; TM=128).
// ---------------------------------------------------------------------------
template<int TM, bool ADD, int OUTMODE>
__global__ __launch_bounds__(256, 1)
void gemm_aggr(const float* __restrict__ A, const float* __restrict__ addv,
               const __nv_bfloat16* __restrict__ Wh, const __nv_bfloat16* __restrict__ Wl,
               const float* __restrict__ bias, float* __restrict__ outp)
{
    extern __shared__ char sm[];
    constexpr int TILEA = TM * ASTR;
    char* pAh = sm;
    char* pAl = sm + TILEA;
    char* pBh = sm + 2 * TILEA;
    char* pBl = pBh + 128 * ASTR;

    const int tid = threadIdx.x;
    const int row0 = blockIdx.x * TM;

    load_B<128>(Wh, Wl, pBh, pBl, tid);
    load_split_A<TM, ADD>(A, addv, row0, pAh, pAl, tid);
    __syncthreads();

    constexpr int WM = TM / 2, MF = WM / 16;
    const int w = tid >> 5, lane = tid & 31;
    const int wm = w >> 2, wn = w & 3;
    const int m0 = wm * WM, n0 = wn * 32;
    const int rr = lane & 7, quad = lane >> 3;
    const uint32_t a_off = (uint32_t)((m0 + rr + ((quad & 1) << 3)) * ASTR + ((quad & 2) << 3));
    const uint32_t b_off = (uint32_t)((n0 + rr + ((quad >> 1) << 3)) * ASTR + ((quad & 1) << 4));

    const uint32_t aAh = smem_u32(pAh), aAl = smem_u32(pAl);
    const uint32_t aBh = smem_u32(pBh), aBl = smem_u32(pBl);

    float acc[MF][4][4];
    #pragma unroll
    for (int mf = 0; mf < MF; ++mf)
        #pragma unroll
        for (int nf = 0; nf < 4; ++nf)
            acc[mf][nf][0] = acc[mf][nf][1] = acc[mf][nf][2] = acc[mf][nf][3] = 0.f;

    mma_3p<MF, 4>(aAh, aAl, aBh, aBl, a_off, b_off, acc);

    const int tq = lane & 3;
    float b0[4], b1[4];
    #pragma unroll
    for (int nf = 0; nf < 4; ++nf) {
        b0[nf] = bias[n0 + nf * 8 + 2 * tq];
        b1[nf] = bias[n0 + nf * 8 + 2 * tq + 1];
    }

    if (OUTMODE == 1) {
        #pragma unroll
        for (int mf = 0; mf < MF; ++mf) {
            const int grp = (row0 + m0 + mf * 16) >> 4;
            #pragma unroll
            for (int nf = 0; nf < 4; ++nf) {
                float s0 = fmaxf(acc[mf][nf][0] + b0[nf], 0.f)
                         + fmaxf(acc[mf][nf][2] + b0[nf], 0.f);
                float s1 = fmaxf(acc[mf][nf][1] + b1[nf], 0.f)
                         + fmaxf(acc[mf][nf][3] + b1[nf], 0.f);
                s0 += __shfl_xor_sync(~0u, s0, 4);  s1 += __shfl_xor_sync(~0u, s1, 4);
                s0 += __shfl_xor_sync(~0u, s0, 8);  s1 += __shfl_xor_sync(~0u, s1, 8);
                s0 += __shfl_xor_sync(~0u, s0, 16); s1 += __shfl_xor_sync(~0u, s1, 16);
                if (lane < 4) {
                    float2 o2 = {s0 * 0.0625f, s1 * 0.0625f};
                    *reinterpret_cast<float2*>(&outp[grp * Hc + n0 + nf * 8 + 2 * lane]) = o2;
                }
            }
        }
    } else {
        float s0[4] = {0,0,0,0}, s1[4] = {0,0,0,0};
        #pragma unroll
        for (int mf = 0; mf < MF; ++mf)
            #pragma unroll
            for (int nf = 0; nf < 4; ++nf) {
                s0[nf] += fmaxf(acc[mf][nf][0] + b0[nf], 0.f)
                        + fmaxf(acc[mf][nf][2] + b0[nf], 0.f);
                s1[nf] += fmaxf(acc[mf][nf][1] + b1[nf], 0.f)
                        + fmaxf(acc[mf][nf][3] + b1[nf], 0.f);
            }
        const int grp = (row0 + m0) >> 6;
        #pragma unroll
        for (int nf = 0; nf < 4; ++nf) {
            float a0 = s0[nf], a1 = s1[nf];
            a0 += __shfl_xor_sync(~0u, a0, 4);  a1 += __shfl_xor_sync(~0u, a1, 4);
            a0 += __shfl_xor_sync(~0u, a0, 8);  a1 += __shfl_xor_sync(~0u, a1, 8);
            a0 += __shfl_xor_sync(~0u, a0, 16); a1 += __shfl_xor_sync(~0u, a1, 16);
            if (lane < 4) {
                float2 o2 = {a0 * (1.f/64.f), a1 * (1.f/64.f)};
                *reinterpret_cast<float2*>(&outp[grp * Hc + n0 + nf * 8 + 2 * lane]) = o2;
            }
        }
    }
}

// ---------------------------------------------------------------------------
// Dual fused GEMM: out = relu( (relu(A@W1+b1) + mean[g]) @ W2 + b2 )
//   MSHIFT: 6 (agent groups) or 4 (user groups)
// ---------------------------------------------------------------------------
template<int TM, bool ADD, int MSHIFT>
__global__ __launch_bounds__(256, 1)
void gemm_dual(const float* __restrict__ A, const float* __restrict__ addv,
               const __nv_bfloat16* __restrict__ W1h, const __nv_bfloat16* __restrict__ W1l,
               const float* __restrict__ b1,
               const float* __restrict__ meanv,
               const __nv_bfloat16* __restrict__ W2h, const __nv_bfloat16* __restrict__ W2l,
               const float* __restrict__ b2,
               float* __restrict__ outp)
{
    extern __shared__ char sm[];
    constexpr int TILEA = TM * ASTR;
    char* pAh = sm;
    char* pAl = sm + TILEA;
    char* pBh = sm + 2 * TILEA;
    char* pBl = pBh + 128 * ASTR;

    const int tid = threadIdx.x;
    const int row0 = blockIdx.x * TM;

    load_B<128>(W1h, W1l, pBh, pBl, tid);
    load_split_A<TM, ADD>(A, addv, row0, pAh, pAl, tid);
    __syncthreads();

    constexpr int WM = TM / 2, MF = WM / 16;
    const int w = tid >> 5, lane = tid & 31;
    const int wm = w >> 2, wn = w & 3;
    const int m0 = wm * WM, n0 = wn * 32;
    const int rr = lane & 7, quad = lane >> 3;
    const uint32_t a_off = (uint32_t)((m0 + rr + ((quad & 1) << 3)) * ASTR + ((quad & 2) << 3));
    const uint32_t b_off = (uint32_t)((n0 + rr + ((quad >> 1) << 3)) * ASTR + ((quad & 1) << 4));

    const uint32_t aAh = smem_u32(pAh), aAl = smem_u32(pAl);
    const uint32_t aBh = smem_u32(pBh), aBl = smem_u32(pBl);

    float acc[MF][4][4];
    #pragma unroll
    for (int mf = 0; mf < MF; ++mf)
        #pragma unroll
        for (int nf = 0; nf < 4; ++nf)
            acc[mf][nf][0] = acc[mf][nf][1] = acc[mf][nf][2] = acc[mf][nf][3] = 0.f;

    mma_3p<MF, 4>(aAh, aAl, aBh, aBl, a_off, b_off, acc);
    __syncthreads();   // all reads of A/B tiles done

    // epilogue1: e = relu(acc + b1) + mean ; re-split into A tiles
    const int tq = lane & 3, gq = lane >> 2;
    #pragma unroll
    for (int mf = 0; mf < MF; ++mf) {
        const int r0 = m0 + mf * 16 + gq;
        const int g = (MSHIFT == 6) ? ((row0 + m0) >> 6)
                                    : ((row0 + m0 + mf * 16) >> 4);
        #pragma unroll
        for (int nf = 0; nf < 4; ++nf) {
            const int c = n0 + nf * 8 + 2 * tq;
            const float2 mv = *reinterpret_cast<const float2*>(&meanv[g * Hc + c]);
            const float bb0 = b1[c], bb1 = b1[c + 1];
            const float e0 = fmaxf(acc[mf][nf][0] + bb0, 0.f) + mv.x;
            const float e1 = fmaxf(acc[mf][nf][1] + bb1, 0.f) + mv.y;
            const float e2 = fmaxf(acc[mf][nf][2] + bb0, 0.f) + mv.x;
            const float e3 = fmaxf(acc[mf][nf][3] + bb1, 0.f) + mv.y;
            uint32_t hi0, lo0, hi1, lo1;
            split2(e0, e1, hi0, lo0);
            split2(e2, e3, hi1, lo1);
            *reinterpret_cast<uint32_t*>(pAh + r0 * ASTR + c * 2) = hi0;
            *reinterpret_cast<uint32_t*>(pAl + r0 * ASTR + c * 2) = lo0;
            *reinterpret_cast<uint32_t*>(pAh + (r0 + 8) * ASTR + c * 2) = hi1;
            *reinterpret_cast<uint32_t*>(pAl + (r0 + 8) * ASTR + c * 2) = lo1;
        }
    }
    load_B<128>(W2h, W2l, pBh, pBl, tid);
    __syncthreads();

    #pragma unroll
    for (int mf = 0; mf < MF; ++mf)
        #pragma unroll
        for (int nf = 0; nf < 4; ++nf)
            acc[mf][nf][0] = acc[mf][nf][1] = acc[mf][nf][2] = acc[mf][nf][3] = 0.f;

    mma_3p<MF, 4>(aAh, aAl, aBh, aBl, a_off, b_off, acc);

    // epilogue2: full store relu(acc + b2)
    #pragma unroll
    for (int mf = 0; mf < MF; ++mf) {
        const int row = row0 + m0 + mf * 16 + gq;
        #pragma unroll
        for (int nf = 0; nf < 4; ++nf) {
            const int c = n0 + nf * 8 + 2 * tq;
            const float bb0 = b2[c], bb1 = b2[c + 1];
            float2 lo, hi;
            lo.x = fmaxf(acc[mf][nf][0] + bb0, 0.f);
            lo.y = fmaxf(acc[mf][nf][1] + bb1, 0.f);
            hi.x = fmaxf(acc[mf][nf][2] + bb0, 0.f);
            hi.y = fmaxf(acc[mf][nf][3] + bb1, 0.f);
            *reinterpret_cast<float2*>(&outp[(size_t)row * Hc + c]) = lo;
            *reinterpret_cast<float2*>(&outp[(size_t)(row + 8) * Hc + c]) = hi;
        }
    }
}

// ---------------------------------------------------------------------------
// Triple fused (conv2 agent + final): A=ha2 ->
//   t = relu(A@W_self+b) + meanA[g]; h = relu(t@W_comb+b); f = h@W_norm'+b_norm;
//   out = (re,im)/|.| using the column-permuted W_norm'.
// TM=128 fixed.
// ---------------------------------------------------------------------------
__global__ __launch_bounds__(256, 1)
void gemm_triple(const float* __restrict__ A,
                 const __nv_bfloat16* __restrict__ W1h, const __nv_bfloat16* __restrict__ W1l,
                 const float* __restrict__ b1,
                 const float* __restrict__ meanv,
                 const __nv_bfloat16* __restrict__ W2h, const __nv_bfloat16* __restrict__ W2l,
                 const float* __restrict__ b2,
                 const __nv_bfloat16* __restrict__ W3h, const __nv_bfloat16* __restrict__ W3l,
                 const float* __restrict__ b3,
                 float* __restrict__ outp)
{
    extern __shared__ char sm[];
    constexpr int TM = 128, TILEA = TM * ASTR;
    char* pAh = sm;
    char* pAl = sm + TILEA;
    char* pBh = sm + 2 * TILEA;
    char* pBl = pBh + 128 * ASTR;

    const int tid = threadIdx.x;
    const int row0 = blockIdx.x * TM;

    load_B<128>(W1h, W1l, pBh, pBl, tid);
    load_split_A<TM, false>(A, nullptr, row0, pAh, pAl, tid);
    __syncthreads();

    constexpr int MF = 4;
    const int w = tid >> 5, lane = tid & 31;
    const int wm = w >> 2, wn = w & 3;
    const int m0 = wm * 64, n0 = wn * 32;
    const int rr = lane & 7, quad = lane >> 3;
    const uint32_t a_off = (uint32_t)((m0 + rr + ((quad & 1) << 3)) * ASTR + ((quad & 2) << 3));
    const uint32_t b_off = (uint32_t)((n0 + rr + ((quad >> 1) << 3)) * ASTR + ((quad & 1) << 4));

    const uint32_t aAh = smem_u32(pAh), aAl = smem_u32(pAl);
    const uint32_t aBh = smem_u32(pBh), aBl = smem_u32(pBl);

    float acc[MF][4][4];
    #pragma unroll
    for (int mf = 0; mf < MF; ++mf)
        #pragma unroll
        for (int nf = 0; nf < 4; ++nf)
            acc[mf][nf][0] = acc[mf][nf][1] = acc[mf][nf][2] = acc[mf][nf][3] = 0.f;
    mma_3p<MF, 4>(aAh, aAl, aBh, aBl, a_off, b_off, acc);
    __syncthreads();

    const int tq = lane & 3, gq = lane >> 2;
    // epilogue1: relu + mean (shift 6), re-split
    #pragma unroll
    for (int mf = 0; mf < MF; ++mf) {
        const int r0 = m0 + mf * 16 + gq;
        const int g = (row0 + m0) >> 6;
        #pragma unroll
        for (int nf = 0; nf < 4; ++nf) {
            const int c = n0 + nf * 8 + 2 * tq;
            const float2 mv = *reinterpret_cast<const float2*>(&meanv[g * Hc + c]);
            const float bb0 = b1[c], bb1 = b1[c + 1];
            const float e0 = fmaxf(acc[mf][nf][0] + bb0, 0.f) + mv.x;
            const float e1 = fmaxf(acc[mf][nf][1] + bb1, 0.f) + mv.y;
            const float e2 = fmaxf(acc[mf][nf][2] + bb0, 0.f) + mv.x;
            const float e3 = fmaxf(acc[mf][nf][3] + bb1, 0.f) + mv.y;
            uint32_t hi0, lo0, hi1, lo1;
            split2(e0, e1, hi0, lo0);
            split2(e2, e3, hi1, lo1);
            *reinterpret_cast<uint32_t*>(pAh + r0 * ASTR + c * 2) = hi0;
            *reinterpret_cast<uint32_t*>(pAl + r0 * ASTR + c * 2) = lo0;
            *reinterpret_cast<uint32_t*>(pAh + (r0 + 8) * ASTR + c * 2) = hi1;
            *reinterpret_cast<uint32_t*>(pAl + (r0 + 8) * ASTR + c * 2) = lo1;
        }
    }
    load_B<128>(W2h, W2l, pBh, pBl, tid);
    __syncthreads();

    #pragma unroll
    for (int mf = 0; mf < MF; ++mf)
        #pragma unroll
        for (int nf = 0; nf < 4; ++nf)
            acc[mf][nf][0] = acc[mf][nf][1] = acc[mf][nf][2] = acc[mf][nf][3] = 0.f;
    mma_3p<MF, 4>(aAh, aAl, aBh, aBl, a_off, b_off, acc);
    __syncthreads();

    // epilogue2: relu(acc + b2) -> re-split
    #pragma unroll
    for (int mf = 0; mf < MF; ++mf) {
        const int r0 = m0 + mf * 16 + gq;
        #pragma unroll
        for (int nf = 0; nf < 4; ++nf) {
            const int c = n0 + nf * 8 + 2 * tq;
            const float bb0 = b2[c], bb1 = b2[c + 1];
            const float e0 = fmaxf(acc[mf][nf][0] + bb0, 0.f);
            const float e1 = fmaxf(acc[mf][nf][1] + bb1, 0.f);
            const float e2 = fmaxf(acc[mf][nf][2] + bb0, 0.f);
            const float e3 = fmaxf(acc[mf][nf][3] + bb1, 0.f);
            uint32_t hi0, lo0, hi1, lo1;
            split2(e0, e1, hi0, lo0);
            split2(e2, e3, hi1, lo1);
            *reinterpret_cast<uint32_t*>(pAh + r0 * ASTR + c * 2) = hi0;
            *reinterpret_cast<uint32_t*>(pAl + r0 * ASTR + c * 2) = lo0;
            *reinterpret_cast<uint32_t*>(pAh + (r0 + 8) * ASTR + c * 2) = hi1;
            *reinterpret_cast<uint32_t*>(pAl + (r0 + 8) * ASTR + c * 2) = lo1;
        }
    }
    load_B<64>(W3h, W3l, pBh, pBl, tid);
    __syncthreads();

    // MMA3: N = 64 (padded; real cols 0..31 = interleaved re/im pairs)
    const int n03 = wn * 16;
    const uint32_t b_off3 = (uint32_t)((n03 + rr + ((quad >> 1) << 3)) * ASTR + ((quad & 1) << 4));
    float acc3[MF][2][4];
    #pragma unroll
    for (int mf = 0; mf < MF; ++mf)
        #pragma unroll
        for (int nf = 0; nf < 2; ++nf)
            acc3[mf][nf][0] = acc3[mf][nf][1] = acc3[mf][nf][2] = acc3[mf][nf][3] = 0.f;
    mma_3p<MF, 2>(aAh, aAl, aBh, aBl, a_off, b_off3, acc3);

    if (wn < 2) {
        #pragma unroll
        for (int mf = 0; mf < MF; ++mf) {
            const int row = row0 + m0 + mf * 16 + gq;
            #pragma unroll
            for (int nf = 0; nf < 2; ++nf) {
                const int c = n03 + nf * 8 + 2 * tq;     // even; rf = c/2
                const int rf = c >> 1;
                const float br = b3[rf], bi = b3[rf + NRFc];
                {
                    const float re = acc3[mf][nf][0] + br;
                    const float im = acc3[mf][nf][1] + bi;
                    const float inv = rsqrtf(re * re + im * im);
                    float2 o = {re * inv, im * inv};
                    *reinterpret_cast<float2*>(&outp[(size_t)row * 32 + c]) = o;
                }
                {
                    const float re = acc3[mf][nf][2] + br;
                    const float im = acc3[mf][nf][3] + bi;
                    const float inv = rsqrtf(re * re + im * im);
                    float2 o = {re * inv, im * inv};
                    *reinterpret_cast<float2*>(&outp[(size_t)(row + 8) * 32 + c]) = o;
                }
            }
        }
    }
}

// ---------------------------------------------------------------------------
// Host
// ---------------------------------------------------------------------------
extern "C" void kernel_launch(void* const* d_in, const int* in_sizes, int n_in,
                              void* d_out, int out_size)
{
    (void)in_sizes; (void)n_in; (void)out_size;

    const float* user_feat = (const float*)d_in[0];
    const float* noise     = (const float*)d_in[1];
    const float* W_ue     = (const float*)d_in[6],  *b_ue     = (const float*)d_in[7];
    const float* W_t      = (const float*)d_in[8],  *b_t      = (const float*)d_in[9];
    const float* b_aggr_a = (const float*)d_in[11];
    const float* b_self_a = (const float*)d_in[13];
    const float* b_comb_a = (const float*)d_in[15];
    const float* b_aggr_u = (const float*)d_in[17];
    const float* b_self_u = (const float*)d_in[19];
    const float* b_comb_u = (const float*)d_in[21];
    const float* W_norm   = (const float*)d_in[22], *b_norm   = (const float*)d_in[23];
    float* out = (float*)d_out;

    float *hu, *hu2, *ha2, *meanA, *meanU, *hag;
    __nv_bfloat16 *wth, *wtl;
    cudaGetSymbolAddress((void**)&hu,    g_hu);
    cudaGetSymbolAddress((void**)&hu2,   g_hu2);
    cudaGetSymbolAddress((void**)&ha2,   g_ha2);
    cudaGetSymbolAddress((void**)&meanA, g_meanA);
    cudaGetSymbolAddress((void**)&meanU, g_meanU);
    cudaGetSymbolAddress((void**)&hag,   g_hag);
    cudaGetSymbolAddress((void**)&wth,   g_wt_hi);
    cudaGetSymbolAddress((void**)&wtl,   g_wt_lo);

    constexpr int SM_PREP  = 128 * 132 * 4;                   // 67584
    constexpr int SM_S1    = 69760;
    constexpr int SM_T64   = (2 * 64 + 2 * 128) * ASTR;       // 104448
    constexpr int SM_T128  = 4 * 128 * ASTR;                  // 139264

    cudaFuncSetAttribute((void*)prep_w, cudaFuncAttributeMaxDynamicSharedMemorySize, SM_PREP);
    cudaFuncSetAttribute((void*)stage1, cudaFuncAttributeMaxDynamicSharedMemorySize, SM_S1);
    cudaFuncSetAttribute((void*)gemm_aggr<64,false,1>, cudaFuncAttributeMaxDynamicSharedMemorySize, SM_T64);
    cudaFuncSetAttribute((void*)gemm_aggr<128,true,2>, cudaFuncAttributeMaxDynamicSharedMemorySize, SM_T128);
    cudaFuncSetAttribute((void*)gemm_dual<128,true,6>, cudaFuncAttributeMaxDynamicSharedMemorySize, SM_T128);
    cudaFuncSetAttribute((void*)gemm_dual<64,false,4>, cudaFuncAttributeMaxDynamicSharedMemorySize, SM_T64);
    cudaFuncSetAttribute((void*)gemm_triple, cudaFuncAttributeMaxDynamicSharedMemorySize, SM_T128);

    const __nv_bfloat16 *WH0 = wth + 0*16384, *WL0 = wtl + 0*16384;   // aggr_a
    const __nv_bfloat16 *WH1 = wth + 1*16384, *WL1 = wtl + 1*16384;   // self_a
    const __nv_bfloat16 *WH2 = wth + 2*16384, *WL2 = wtl + 2*16384;   // comb_a
    const __nv_bfloat16 *WH3 = wth + 3*16384, *WL3 = wtl + 3*16384;   // aggr_u
    const __nv_bfloat16 *WH4 = wth + 4*16384, *WL4 = wtl + 4*16384;   // self_u
    const __nv_bfloat16 *WH5 = wth + 5*16384, *WL5 = wtl + 5*16384;   // comb_u
    const __nv_bfloat16 *WH6 = wth + 6*16384, *WL6 = wtl + 6*16384;   // W_norm'

    // 1) weight transpose + hi/lo split (+ permuted W_norm)
    prep_w<<<7, 256, SM_PREP>>>((const float*)d_in[10], (const float*)d_in[12],
                                (const float*)d_in[14], (const float*)d_in[16],
                                (const float*)d_in[18], (const float*)d_in[20],
                                W_norm, wth, wtl);
    // 2) hu + mean16 + hag
    stage1<<<NUSER/128, 256, SM_S1>>>(user_feat, W_ue, b_ue, W_t, b_t, hu, hag);
    // 3) conv1: meanA = mean16(relu(hu @ W_aggr_a + b))
    gemm_aggr<64,false,1><<<NUSER/64, 256, SM_T64>>>(hu, nullptr, WH0, WL0, b_aggr_a, meanA);
    // 4) conv1 agent: ha2 = relu((relu((noise+hag)@W_self_a+b) + meanA) @ W_comb_a + b)
    gemm_dual<128,true,6><<<NAG/128, 256, SM_T128>>>(noise, hag, WH1, WL1, b_self_a,
                                                     meanA, WH2, WL2, b_comb_a, ha2);
    // 5) conv1: meanU = mean64(relu((noise+hag) @ W_aggr_u + b))
    gemm_aggr<128,true,2><<<NAG/128, 256, SM_T128>>>(noise, hag, WH3, WL3, b_aggr_u, meanU);
    // 6) conv1 user: hu2 = relu((relu(hu@W_self_u+b) + meanU) @ W_comb_u + b)
    gemm_dual<64,false,4><<<NUSER/64, 256, SM_T64>>>(hu, nullptr, WH4, WL4, b_self_u,
                                                     meanU, WH5, WL5, b_comb_u, hu2);
    // 7) conv2: meanA = mean16(relu(hu2 @ W_aggr_a + b))
    gemm_aggr<64,false,1><<<NUSER/64, 256, SM_T64>>>(hu2, nullptr, WH0, WL0, b_aggr_a, meanA);
    // 8) conv2 agent + final projection + normalize -> out
    gemm_triple<<<NAG/128, 256, SM_T128>>>(ha2, WH1, WL1, b_self_a, meanA,
                                           WH2, WL2, b_comb_a, WH6, WL6, b_norm, out);
}